// round 3
// baseline (speedup 1.0000x reference)
#include <cuda_runtime.h>
#include <math.h>

#define H      64
#define DIN    128
#define EPSBN  1e-5f
#define MAXN   50048
#define MAXE   1200128
#define MAXG   64

// ---------------- scratch (static __device__, no runtime allocs) ----------------
__device__ float g_h  [MAXN * H];
__device__ float g_hg [MAXN * H];
__device__ float g_hs [MAXN * H];
__device__ float g_tmp[MAXN * H];
__device__ int   g_indeg[MAXN];
__device__ int   g_fill [MAXN];
__device__ int   g_rowptr[MAXN + 1];
__device__ int   g_col  [MAXE];
__device__ float g_dinv [MAXN];
__device__ float g_pool [MAXG * 2 * H];
__device__ int   g_gcnt [MAXG];
__device__ int   g_scanbuf[MAXN];
__device__ int   g_blocksums[256];

// ---------------- setup kernels ----------------
__global__ void k_zero(int n, int g) {
    int i = blockIdx.x * blockDim.x + threadIdx.x;
    if (i < n) { g_indeg[i] = 0; g_fill[i] = 0; }
    if (i < g * 2 * H) g_pool[i] = 0.f;
    if (i < g) g_gcnt[i] = 0;
}

__global__ void k_deg(const int* __restrict__ dst, const int* __restrict__ batch,
                      int E, int N) {
    int i = blockIdx.x * blockDim.x + threadIdx.x;
    if (i < E) atomicAdd(&g_indeg[dst[i]], 1);
    if (i < N) atomicAdd(&g_gcnt[batch[i]], 1);
}

// block-wise inclusive scan of indeg; also compute dinv = rsqrt(indeg+1)
__global__ void k_scan1(int N) {
    __shared__ int sh[256];
    int t = threadIdx.x;
    int i = blockIdx.x * 256 + t;
    int v = (i < N) ? g_indeg[i] : 0;
    sh[t] = v; __syncthreads();
#pragma unroll
    for (int off = 1; off < 256; off <<= 1) {
        int a = 0;
        if (t >= off) a = sh[t - off];
        __syncthreads();
        sh[t] += a;
        __syncthreads();
    }
    if (i < N) {
        g_scanbuf[i] = sh[t];
        g_dinv[i] = rsqrtf((float)(v + 1));
    }
    if (t == 255) g_blocksums[blockIdx.x] = sh[255];
}

// exclusive scan of block sums (nb <= 256)
__global__ void k_scan2(int nb) {
    __shared__ int sh[256];
    int t = threadIdx.x;
    int v = (t < nb) ? g_blocksums[t] : 0;
    sh[t] = v; __syncthreads();
#pragma unroll
    for (int off = 1; off < 256; off <<= 1) {
        int a = 0;
        if (t >= off) a = sh[t - off];
        __syncthreads();
        sh[t] += a;
        __syncthreads();
    }
    if (t < nb) g_blocksums[t] = sh[t] - v;   // exclusive
}

__global__ void k_rowptr(int N) {
    int i = blockIdx.x * 256 + threadIdx.x;
    if (i < N) g_rowptr[i + 1] = g_scanbuf[i] + g_blocksums[blockIdx.x];
    if (i == 0) g_rowptr[0] = 0;
}

__global__ void k_fill(const int* __restrict__ src, const int* __restrict__ dst, int E) {
    int e = blockIdx.x * blockDim.x + threadIdx.x;
    if (e < E) {
        int d = dst[e];
        int pos = atomicAdd(&g_fill[d], 1);
        g_col[g_rowptr[d] + pos] = src[e];
    }
}

// ---------------- GEMM kernels ----------------
// h = relu(x @ W_in + b_in),  x:[n,128], W:[128,64]
__global__ void k_gemm_in(const float* __restrict__ X, const float* __restrict__ W,
                          const float* __restrict__ b, float* __restrict__ out, int n) {
    __shared__ float Ws[64][64];
    __shared__ float Xs[64][64];
    int r0 = blockIdx.x * 64;
    int ty = threadIdx.x / 16, tx = threadIdx.x % 16;
    float acc[4][4] = {};
    for (int kk = 0; kk < DIN; kk += 64) {
        // stage W chunk (rows kk..kk+63, contiguous)
        const float4* Wg = (const float4*)(W + kk * 64);
        float4* Wsv = (float4*)Ws;
        for (int t = threadIdx.x; t < 1024; t += 256) Wsv[t] = Wg[t];
        // stage X chunk
        for (int t = threadIdx.x; t < 1024; t += 256) {
            int row = t / 16, c4 = t % 16;
            int r = r0 + row;
            float4 v = make_float4(0.f, 0.f, 0.f, 0.f);
            if (r < n) v = *(const float4*)(X + (long)r * DIN + kk + c4 * 4);
            *(float4*)&Xs[row][c4 * 4] = v;
        }
        __syncthreads();
#pragma unroll
        for (int k = 0; k < 64; k++) {
            float4 w = *(const float4*)&Ws[k][tx * 4];
#pragma unroll
            for (int i = 0; i < 4; i++) {
                float a = Xs[ty * 4 + i][k];
                acc[i][0] += a * w.x; acc[i][1] += a * w.y;
                acc[i][2] += a * w.z; acc[i][3] += a * w.w;
            }
        }
        __syncthreads();
    }
#pragma unroll
    for (int i = 0; i < 4; i++) {
        int r = r0 + ty * 4 + i;
        if (r < n) {
            float4 o;
            o.x = fmaxf(acc[i][0] + b[tx * 4 + 0], 0.f);
            o.y = fmaxf(acc[i][1] + b[tx * 4 + 1], 0.f);
            o.z = fmaxf(acc[i][2] + b[tx * 4 + 2], 0.f);
            o.w = fmaxf(acc[i][3] + b[tx * 4 + 3], 0.f);
            *(float4*)&out[(long)r * H + tx * 4] = o;
        }
    }
}

// tmp = (X @ W) * dinv[row]     X:[n,64], W:[64,64]
__global__ void k_gemm64_scale(const float* __restrict__ X, const float* __restrict__ W,
                               float* __restrict__ out, int n) {
    __shared__ float Ws[64][64];
    __shared__ float Xs[64][64];
    int r0 = blockIdx.x * 64;
    int ty = threadIdx.x / 16, tx = threadIdx.x % 16;
    float acc[4][4] = {};
    {
        const float4* Wg = (const float4*)W;
        float4* Wsv = (float4*)Ws;
        for (int t = threadIdx.x; t < 1024; t += 256) Wsv[t] = Wg[t];
        for (int t = threadIdx.x; t < 1024; t += 256) {
            int row = t / 16, c4 = t % 16;
            int r = r0 + row;
            float4 v = make_float4(0.f, 0.f, 0.f, 0.f);
            if (r < n) v = *(const float4*)(X + (long)r * H + c4 * 4);
            *(float4*)&Xs[row][c4 * 4] = v;
        }
        __syncthreads();
#pragma unroll
        for (int k = 0; k < 64; k++) {
            float4 w = *(const float4*)&Ws[k][tx * 4];
#pragma unroll
            for (int i = 0; i < 4; i++) {
                float a = Xs[ty * 4 + i][k];
                acc[i][0] += a * w.x; acc[i][1] += a * w.y;
                acc[i][2] += a * w.z; acc[i][3] += a * w.w;
            }
        }
    }
#pragma unroll
    for (int i = 0; i < 4; i++) {
        int r = r0 + ty * 4 + i;
        if (r < n) {
            float s = g_dinv[r];
            float4 o = make_float4(acc[i][0] * s, acc[i][1] * s, acc[i][2] * s, acc[i][3] * s);
            *(float4*)&out[(long)r * H + tx * 4] = o;
        }
    }
}

// hs_out = relu(BN(mean @ Wl + hs @ Wr + b))
__global__ void k_sage_gemm(const float* __restrict__ Mean, const float* __restrict__ Wl,
                            const float* __restrict__ Hs, const float* __restrict__ Wr,
                            const float* __restrict__ bias, const float* __restrict__ bn,
                            float* __restrict__ out, int n) {
    __shared__ float Wls[64][64];
    __shared__ float Wrs[64][64];
    __shared__ float Xs[64][64];
    int r0 = blockIdx.x * 64;
    int ty = threadIdx.x / 16, tx = threadIdx.x % 16;
    float acc[4][4] = {};
    {
        const float4* w1 = (const float4*)Wl;
        const float4* w2 = (const float4*)Wr;
        for (int t = threadIdx.x; t < 1024; t += 256) {
            ((float4*)Wls)[t] = w1[t];
            ((float4*)Wrs)[t] = w2[t];
        }
    }
    // pass 1: mean @ Wl
    for (int t = threadIdx.x; t < 1024; t += 256) {
        int row = t / 16, c4 = t % 16;
        int r = r0 + row;
        float4 v = make_float4(0.f, 0.f, 0.f, 0.f);
        if (r < n) v = *(const float4*)(Mean + (long)r * H + c4 * 4);
        *(float4*)&Xs[row][c4 * 4] = v;
    }
    __syncthreads();
#pragma unroll
    for (int k = 0; k < 64; k++) {
        float4 w = *(const float4*)&Wls[k][tx * 4];
#pragma unroll
        for (int i = 0; i < 4; i++) {
            float a = Xs[ty * 4 + i][k];
            acc[i][0] += a * w.x; acc[i][1] += a * w.y;
            acc[i][2] += a * w.z; acc[i][3] += a * w.w;
        }
    }
    __syncthreads();
    // pass 2: hs @ Wr
    for (int t = threadIdx.x; t < 1024; t += 256) {
        int row = t / 16, c4 = t % 16;
        int r = r0 + row;
        float4 v = make_float4(0.f, 0.f, 0.f, 0.f);
        if (r < n) v = *(const float4*)(Hs + (long)r * H + c4 * 4);
        *(float4*)&Xs[row][c4 * 4] = v;
    }
    __syncthreads();
#pragma unroll
    for (int k = 0; k < 64; k++) {
        float4 w = *(const float4*)&Wrs[k][tx * 4];
#pragma unroll
        for (int i = 0; i < 4; i++) {
            float a = Xs[ty * 4 + i][k];
            acc[i][0] += a * w.x; acc[i][1] += a * w.y;
            acc[i][2] += a * w.z; acc[i][3] += a * w.w;
        }
    }
    // epilogue: bias + BN + relu
    float gam[4], bet[4], rm[4], rvs[4], bb[4];
#pragma unroll
    for (int j = 0; j < 4; j++) {
        int c = tx * 4 + j;
        gam[j] = bn[c]; bet[j] = bn[64 + c]; rm[j] = bn[128 + c];
        rvs[j] = rsqrtf(bn[192 + c] + EPSBN);
        bb[j] = bias[c];
    }
#pragma unroll
    for (int i = 0; i < 4; i++) {
        int r = r0 + ty * 4 + i;
        if (r < n) {
            float4 o;
            float v0 = (acc[i][0] + bb[0] - rm[0]) * rvs[0] * gam[0] + bet[0];
            float v1 = (acc[i][1] + bb[1] - rm[1]) * rvs[1] * gam[1] + bet[1];
            float v2 = (acc[i][2] + bb[2] - rm[2]) * rvs[2] * gam[2] + bet[2];
            float v3 = (acc[i][3] + bb[3] - rm[3]) * rvs[3] * gam[3] + bet[3];
            o.x = fmaxf(v0, 0.f); o.y = fmaxf(v1, 0.f);
            o.z = fmaxf(v2, 0.f); o.w = fmaxf(v3, 0.f);
            *(float4*)&out[(long)r * H + tx * 4] = o;
        }
    }
}

// ---------------- aggregation kernels ----------------
// GCN: out[d] = relu(BN( dinv[d]*(sum_nbr tmp[s] + tmp[d]) + b ))   (tmp pre-scaled by dinv)
__global__ void k_gcn_agg(const float* __restrict__ tmp, const float* __restrict__ bias,
                          const float* __restrict__ bn, float* __restrict__ out, int n) {
    int d = blockIdx.x * 4 + (threadIdx.x >> 6);
    int c = threadIdx.x & 63;
    if (d >= n) return;
    int beg = g_rowptr[d], end = g_rowptr[d + 1];
    float acc = tmp[(long)d * H + c];   // self-loop term
    float a0 = 0.f, a1 = 0.f, a2 = 0.f, a3 = 0.f;
    int j = beg;
    for (; j + 3 < end; j += 4) {
        int s0 = g_col[j], s1 = g_col[j + 1], s2 = g_col[j + 2], s3 = g_col[j + 3];
        a0 += tmp[(long)s0 * H + c];
        a1 += tmp[(long)s1 * H + c];
        a2 += tmp[(long)s2 * H + c];
        a3 += tmp[(long)s3 * H + c];
    }
    for (; j < end; j++) acc += tmp[(long)g_col[j] * H + c];
    acc += (a0 + a1) + (a2 + a3);
    float v = acc * g_dinv[d] + bias[c];
    v = (v - bn[128 + c]) * rsqrtf(bn[192 + c] + EPSBN) * bn[c] + bn[64 + c];
    out[(long)d * H + c] = fmaxf(v, 0.f);
}

// SAGE mean aggregation: mean[d] = sum_nbr hs[s] / max(indeg,1)
__global__ void k_sage_agg(const float* __restrict__ X, float* __restrict__ out, int n) {
    int d = blockIdx.x * 4 + (threadIdx.x >> 6);
    int c = threadIdx.x & 63;
    if (d >= n) return;
    int beg = g_rowptr[d], end = g_rowptr[d + 1];
    float a0 = 0.f, a1 = 0.f, a2 = 0.f, a3 = 0.f;
    float acc = 0.f;
    int j = beg;
    for (; j + 3 < end; j += 4) {
        int s0 = g_col[j], s1 = g_col[j + 1], s2 = g_col[j + 2], s3 = g_col[j + 3];
        a0 += X[(long)s0 * H + c];
        a1 += X[(long)s1 * H + c];
        a2 += X[(long)s2 * H + c];
        a3 += X[(long)s3 * H + c];
    }
    for (; j < end; j++) acc += X[(long)g_col[j] * H + c];
    acc += (a0 + a1) + (a2 + a3);
    float inv = 1.f / fmaxf((float)(end - beg), 1.f);
    out[(long)d * H + c] = acc * inv;
}

// ---------------- pooling (batch is sorted -> run-flush) ----------------
__global__ void k_pool(const float* __restrict__ hg, const float* __restrict__ hs,
                       const int* __restrict__ batch, int n) {
    int c = threadIdx.x & 63;
    int nl = threadIdx.x >> 6;
    int i0 = blockIdx.x * 256 + nl * 64;
    float ag = 0.f, as = 0.f;
    int cur = -1;
    for (int k = 0; k < 64; k++) {
        int i = i0 + k;
        if (i >= n) break;
        int g = batch[i];
        if (g != cur) {
            if (cur >= 0) {
                atomicAdd(&g_pool[cur * 128 + c], ag);
                atomicAdd(&g_pool[cur * 128 + 64 + c], as);
            }
            cur = g; ag = 0.f; as = 0.f;
        }
        ag += hg[(long)i * H + c];
        as += hs[(long)i * H + c];
    }
    if (cur >= 0) {
        atomicAdd(&g_pool[cur * 128 + c], ag);
        atomicAdd(&g_pool[cur * 128 + 64 + c], as);
    }
}

// ---------------- final MLP (one block per graph) ----------------
__global__ void k_mlp(const float* __restrict__ fc1W, const float* __restrict__ fc1b,
                      const float* __restrict__ bn1,
                      const float* __restrict__ fc2W, const float* __restrict__ fc2b,
                      const float* __restrict__ bn2,
                      const float* __restrict__ fc3W, const float* __restrict__ fc3b,
                      float* __restrict__ out) {
    int g = blockIdx.x;
    int t = threadIdx.x;  // 64 threads
    __shared__ float z[128];
    __shared__ float s1[64];
    __shared__ float s2[32];
    float inv = 1.f / fmaxf((float)g_gcnt[g], 1.f);
    z[t]      = g_pool[g * 128 + t] * inv;
    z[t + 64] = g_pool[g * 128 + 64 + t] * inv;
    __syncthreads();
    // fc1 + bn1 + relu
    float acc = fc1b[t];
#pragma unroll 8
    for (int k = 0; k < 128; k++) acc += z[k] * fc1W[k * 64 + t];
    acc = (acc - bn1[128 + t]) * rsqrtf(bn1[192 + t] + EPSBN) * bn1[t] + bn1[64 + t];
    s1[t] = fmaxf(acc, 0.f);
    __syncthreads();
    // fc2 + bn2 + relu
    if (t < 32) {
        float a = fc2b[t];
#pragma unroll 8
        for (int k = 0; k < 64; k++) a += s1[k] * fc2W[k * 32 + t];
        a = (a - bn2[64 + t]) * rsqrtf(bn2[96 + t] + EPSBN) * bn2[t] + bn2[32 + t];
        s2[t] = fmaxf(a, 0.f);
    }
    __syncthreads();
    // fc3 (dot of 32) via warp reduce in warp 0
    if (t < 32) {
        float p = s2[t] * fc3W[t];
#pragma unroll
        for (int o = 16; o > 0; o >>= 1) p += __shfl_down_sync(0xffffffffu, p, o);
        if (t == 0) out[g] = p + fc3b[0];
    }
}

// ---------------- launch ----------------
extern "C" void kernel_launch(void* const* d_in, const int* in_sizes, int n_in,
                              void* d_out, int out_size) {
    const float* x     = (const float*)d_in[0];
    const int*   ei    = (const int*)d_in[1];
    const int*   batch = (const int*)d_in[2];
    const float* W_in  = (const float*)d_in[3];
    const float* b_in  = (const float*)d_in[4];
    const float* gcn_W = (const float*)d_in[5];
    const float* gcn_b = (const float*)d_in[6];
    const float* gcn_bn= (const float*)d_in[7];
    const float* sg_Wl = (const float*)d_in[8];
    const float* sg_Wr = (const float*)d_in[9];
    const float* sg_b  = (const float*)d_in[10];
    const float* sg_bn = (const float*)d_in[11];
    const float* fc1W  = (const float*)d_in[12];
    const float* fc1b  = (const float*)d_in[13];
    const float* bn1   = (const float*)d_in[14];
    const float* fc2W  = (const float*)d_in[15];
    const float* fc2b  = (const float*)d_in[16];
    const float* bn2   = (const float*)d_in[17];
    const float* fc3W  = (const float*)d_in[18];
    const float* fc3b  = (const float*)d_in[19];
    float* out = (float*)d_out;

    int N = in_sizes[0] / DIN;
    int E = in_sizes[1] / 2;
    int G = out_size;
    const int* src = ei;
    const int* dst = ei + E;

    float *d_h, *d_hg, *d_hs, *d_tmp;
    cudaGetSymbolAddress((void**)&d_h,   g_h);
    cudaGetSymbolAddress((void**)&d_hg,  g_hg);
    cudaGetSymbolAddress((void**)&d_hs,  g_hs);
    cudaGetSymbolAddress((void**)&d_tmp, g_tmp);

    int nbN   = (N + 255) / 256;
    int nbE   = ((E > N ? E : N) + 255) / 256;
    int nbG64 = (N + 63) / 64;
    int nbAgg = (N + 3) / 4;

    // CSR build + degrees
    k_zero<<<nbN, 256>>>(N, G);
    k_deg<<<nbE, 256>>>(dst, batch, E, N);
    k_scan1<<<nbN, 256>>>(N);
    k_scan2<<<1, 256>>>(nbN);
    k_rowptr<<<nbN, 256>>>(N);
    k_fill<<<(E + 255) / 256, 256>>>(src, dst, E);

    // input projection
    k_gemm_in<<<nbG64, 256>>>(x, W_in, b_in, d_h, N);

    // GCN branch (2 layers)
    k_gemm64_scale<<<nbG64, 256>>>(d_h, gcn_W, d_tmp, N);
    k_gcn_agg<<<nbAgg, 256>>>(d_tmp, gcn_b, gcn_bn, d_hg, N);
    k_gemm64_scale<<<nbG64, 256>>>(d_hg, gcn_W + 64 * 64, d_tmp, N);
    k_gcn_agg<<<nbAgg, 256>>>(d_tmp, gcn_b + 64, gcn_bn + 256, d_hg, N);

    // SAGE branch (2 layers)
    k_sage_agg<<<nbAgg, 256>>>(d_h, d_tmp, N);
    k_sage_gemm<<<nbG64, 256>>>(d_tmp, sg_Wl, d_h, sg_Wr, sg_b, sg_bn, d_hs, N);
    k_sage_agg<<<nbAgg, 256>>>(d_hs, d_tmp, N);
    k_sage_gemm<<<nbG64, 256>>>(d_tmp, sg_Wl + 64 * 64, d_hs, sg_Wr + 64 * 64,
                                sg_b + 64, sg_bn + 256, d_hs, N);

    // pooling + MLP head
    k_pool<<<nbN, 256>>>(d_hg, d_hs, batch, N);
    k_mlp<<<G, 64>>>(fc1W, fc1b, bn1, fc2W, fc2b, bn2, fc3W, fc3b, out);
}

// round 4
// speedup vs baseline: 1.2402x; 1.2402x over previous
#include <cuda_runtime.h>
#include <cuda_bf16.h>
#include <math.h>

#define H      64
#define DIN    128
#define EPSBN  1e-5f
#define MAXN   50048
#define MAXE   1200128
#define MAXG   64

// ---------------- scratch (static __device__, no runtime allocs) ----------------
__device__ float g_h  [MAXN * H];      // relu(x@W_in) fp32
__device__ float g_hs [MAXN * H];      // sage hidden fp32 (in-place across layers)
__device__ float g_hg [MAXN * H];      // gcn final fp32
__device__ float g_tG [MAXN * H];      // gcn agg scratch fp32
__device__ float g_tS [MAXN * H];      // sage agg scratch fp32
__device__ __nv_bfloat162 g_h16 [MAXN * 32];  // bf16 staged h
__device__ __nv_bfloat162 g_hg16[MAXN * 32];  // bf16 staged dinv*hg (prescaled)
__device__ __nv_bfloat162 g_hs16[MAXN * 32];  // bf16 staged hs
__device__ int   g_indeg[MAXN];
__device__ int   g_fill [MAXN];
__device__ int   g_rowptr[MAXN + 1];
__device__ int   g_col  [MAXE];
__device__ float g_dinv [MAXN];
__device__ float g_pool [MAXG * 2 * H];
__device__ int   g_gcnt [MAXG];
__device__ int   g_scanbuf[MAXN];
__device__ int   g_blocksums[256];

// ---------------- setup kernels ----------------
__global__ void k_zero(int n, int g) {
    int i = blockIdx.x * blockDim.x + threadIdx.x;
    if (i < n) { g_indeg[i] = 0; g_fill[i] = 0; }
    if (i < g * 2 * H) g_pool[i] = 0.f;
    if (i < g) g_gcnt[i] = 0;
}

__global__ void k_deg(const int* __restrict__ dst, const int* __restrict__ batch,
                      int E, int N) {
    int i = blockIdx.x * blockDim.x + threadIdx.x;
    if (i < E) atomicAdd(&g_indeg[dst[i]], 1);
    if (i < N) atomicAdd(&g_gcnt[batch[i]], 1);
}

__global__ void k_scan1(int N) {
    __shared__ int sh[256];
    int t = threadIdx.x;
    int i = blockIdx.x * 256 + t;
    int v = (i < N) ? g_indeg[i] : 0;
    sh[t] = v; __syncthreads();
#pragma unroll
    for (int off = 1; off < 256; off <<= 1) {
        int a = 0;
        if (t >= off) a = sh[t - off];
        __syncthreads();
        sh[t] += a;
        __syncthreads();
    }
    if (i < N) {
        g_scanbuf[i] = sh[t];
        g_dinv[i] = rsqrtf((float)(v + 1));
    }
    if (t == 255) g_blocksums[blockIdx.x] = sh[255];
}

__global__ void k_scan2(int nb) {
    __shared__ int sh[256];
    int t = threadIdx.x;
    int v = (t < nb) ? g_blocksums[t] : 0;
    sh[t] = v; __syncthreads();
#pragma unroll
    for (int off = 1; off < 256; off <<= 1) {
        int a = 0;
        if (t >= off) a = sh[t - off];
        __syncthreads();
        sh[t] += a;
        __syncthreads();
    }
    if (t < nb) g_blocksums[t] = sh[t] - v;   // exclusive
}

__global__ void k_rowptr(int N) {
    int i = blockIdx.x * 256 + threadIdx.x;
    if (i < N) g_rowptr[i + 1] = g_scanbuf[i] + g_blocksums[blockIdx.x];
    if (i == 0) g_rowptr[0] = 0;
}

__global__ void k_fill(const int* __restrict__ src, const int* __restrict__ dst, int E) {
    int e = blockIdx.x * blockDim.x + threadIdx.x;
    if (e < E) {
        int d = dst[e];
        int pos = atomicAdd(&g_fill[d], 1);
        g_col[g_rowptr[d] + pos] = src[e];
    }
}

// ---------------- GEMM kernels ----------------
// h = relu(x @ W_in + b_in)  -> fp32 out + bf16 staged copy
__global__ void k_gemm_in(const float* __restrict__ X, const float* __restrict__ W,
                          const float* __restrict__ b, float* __restrict__ out,
                          __nv_bfloat162* __restrict__ out16, int n) {
    __shared__ float Ws[64][64];
    __shared__ float Xs[64][64];
    int r0 = blockIdx.x * 64;
    int ty = threadIdx.x / 16, tx = threadIdx.x % 16;
    float acc[4][4] = {};
    for (int kk = 0; kk < DIN; kk += 64) {
        const float4* Wg = (const float4*)(W + kk * 64);
        float4* Wsv = (float4*)Ws;
        for (int t = threadIdx.x; t < 1024; t += 256) Wsv[t] = Wg[t];
        for (int t = threadIdx.x; t < 1024; t += 256) {
            int row = t / 16, c4 = t % 16;
            int r = r0 + row;
            float4 v = make_float4(0.f, 0.f, 0.f, 0.f);
            if (r < n) v = *(const float4*)(X + (long)r * DIN + kk + c4 * 4);
            *(float4*)&Xs[row][c4 * 4] = v;
        }
        __syncthreads();
#pragma unroll
        for (int k = 0; k < 64; k++) {
            float4 w = *(const float4*)&Ws[k][tx * 4];
#pragma unroll
            for (int i = 0; i < 4; i++) {
                float a = Xs[ty * 4 + i][k];
                acc[i][0] += a * w.x; acc[i][1] += a * w.y;
                acc[i][2] += a * w.z; acc[i][3] += a * w.w;
            }
        }
        __syncthreads();
    }
#pragma unroll
    for (int i = 0; i < 4; i++) {
        int r = r0 + ty * 4 + i;
        if (r < n) {
            float4 o;
            o.x = fmaxf(acc[i][0] + b[tx * 4 + 0], 0.f);
            o.y = fmaxf(acc[i][1] + b[tx * 4 + 1], 0.f);
            o.z = fmaxf(acc[i][2] + b[tx * 4 + 2], 0.f);
            o.w = fmaxf(acc[i][3] + b[tx * 4 + 3], 0.f);
            *(float4*)&out[(long)r * H + tx * 4] = o;
            out16[r * 32 + tx * 2]     = __floats2bfloat162_rn(o.x, o.y);
            out16[r * 32 + tx * 2 + 1] = __floats2bfloat162_rn(o.z, o.w);
        }
    }
}

// GCN GEMM: out = relu(BN(A @ W + b)).
// If out16 != null: write bf16 staged copy pre-scaled by dinv[row] (for next gather).
// If outf  != null: write fp32.
__global__ void k_gcn_gemm(const float* __restrict__ A, const float* __restrict__ W,
                           const float* __restrict__ bias, const float* __restrict__ bn,
                           float* __restrict__ outf, __nv_bfloat162* __restrict__ out16,
                           int n) {
    __shared__ float Ws[64][64];
    __shared__ float Xs[64][64];
    int r0 = blockIdx.x * 64;
    int ty = threadIdx.x / 16, tx = threadIdx.x % 16;
    float acc[4][4] = {};
    {
        const float4* Wg = (const float4*)W;
        for (int t = threadIdx.x; t < 1024; t += 256) ((float4*)Ws)[t] = Wg[t];
        for (int t = threadIdx.x; t < 1024; t += 256) {
            int row = t / 16, c4 = t % 16;
            int r = r0 + row;
            float4 v = make_float4(0.f, 0.f, 0.f, 0.f);
            if (r < n) v = *(const float4*)(A + (long)r * H + c4 * 4);
            *(float4*)&Xs[row][c4 * 4] = v;
        }
        __syncthreads();
#pragma unroll
        for (int k = 0; k < 64; k++) {
            float4 w = *(const float4*)&Ws[k][tx * 4];
#pragma unroll
            for (int i = 0; i < 4; i++) {
                float a = Xs[ty * 4 + i][k];
                acc[i][0] += a * w.x; acc[i][1] += a * w.y;
                acc[i][2] += a * w.z; acc[i][3] += a * w.w;
            }
        }
    }
    float gam[4], bet[4], rm[4], rvs[4], bb[4];
#pragma unroll
    for (int j = 0; j < 4; j++) {
        int c = tx * 4 + j;
        gam[j] = bn[c]; bet[j] = bn[64 + c]; rm[j] = bn[128 + c];
        rvs[j] = rsqrtf(bn[192 + c] + EPSBN);
        bb[j] = bias[c];
    }
#pragma unroll
    for (int i = 0; i < 4; i++) {
        int r = r0 + ty * 4 + i;
        if (r < n) {
            float v0 = fmaxf((acc[i][0] + bb[0] - rm[0]) * rvs[0] * gam[0] + bet[0], 0.f);
            float v1 = fmaxf((acc[i][1] + bb[1] - rm[1]) * rvs[1] * gam[1] + bet[1], 0.f);
            float v2 = fmaxf((acc[i][2] + bb[2] - rm[2]) * rvs[2] * gam[2] + bet[2], 0.f);
            float v3 = fmaxf((acc[i][3] + bb[3] - rm[3]) * rvs[3] * gam[3] + bet[3], 0.f);
            if (outf) *(float4*)&outf[(long)r * H + tx * 4] = make_float4(v0, v1, v2, v3);
            if (out16) {
                float s = g_dinv[r];
                out16[r * 32 + tx * 2]     = __floats2bfloat162_rn(v0 * s, v1 * s);
                out16[r * 32 + tx * 2 + 1] = __floats2bfloat162_rn(v2 * s, v3 * s);
            }
        }
    }
}

// SAGE GEMM: out = relu(BN(Mean @ Wl + Hs @ Wr + b)).  In-place on Hs is safe
// (each block reads exactly the rows it later writes, separated by __syncthreads).
__global__ void k_sage_gemm(const float* __restrict__ Mean, const float* __restrict__ Wl,
                            const float* __restrict__ Hs, const float* __restrict__ Wr,
                            const float* __restrict__ bias, const float* __restrict__ bn,
                            float* __restrict__ out, __nv_bfloat162* __restrict__ out16,
                            int n) {
    __shared__ float Wls[64][64];
    __shared__ float Wrs[64][64];
    __shared__ float Xs[64][64];
    int r0 = blockIdx.x * 64;
    int ty = threadIdx.x / 16, tx = threadIdx.x % 16;
    float acc[4][4] = {};
    {
        const float4* w1 = (const float4*)Wl;
        const float4* w2 = (const float4*)Wr;
        for (int t = threadIdx.x; t < 1024; t += 256) {
            ((float4*)Wls)[t] = w1[t];
            ((float4*)Wrs)[t] = w2[t];
        }
    }
    // pass 1: Mean @ Wl
    for (int t = threadIdx.x; t < 1024; t += 256) {
        int row = t / 16, c4 = t % 16;
        int r = r0 + row;
        float4 v = make_float4(0.f, 0.f, 0.f, 0.f);
        if (r < n) v = *(const float4*)(Mean + (long)r * H + c4 * 4);
        *(float4*)&Xs[row][c4 * 4] = v;
    }
    __syncthreads();
#pragma unroll
    for (int k = 0; k < 64; k++) {
        float4 w = *(const float4*)&Wls[k][tx * 4];
#pragma unroll
        for (int i = 0; i < 4; i++) {
            float a = Xs[ty * 4 + i][k];
            acc[i][0] += a * w.x; acc[i][1] += a * w.y;
            acc[i][2] += a * w.z; acc[i][3] += a * w.w;
        }
    }
    __syncthreads();
    // pass 2: Hs @ Wr
    for (int t = threadIdx.x; t < 1024; t += 256) {
        int row = t / 16, c4 = t % 16;
        int r = r0 + row;
        float4 v = make_float4(0.f, 0.f, 0.f, 0.f);
        if (r < n) v = *(const float4*)(Hs + (long)r * H + c4 * 4);
        *(float4*)&Xs[row][c4 * 4] = v;
    }
    __syncthreads();
#pragma unroll
    for (int k = 0; k < 64; k++) {
        float4 w = *(const float4*)&Wrs[k][tx * 4];
#pragma unroll
        for (int i = 0; i < 4; i++) {
            float a = Xs[ty * 4 + i][k];
            acc[i][0] += a * w.x; acc[i][1] += a * w.y;
            acc[i][2] += a * w.z; acc[i][3] += a * w.w;
        }
    }
    float gam[4], bet[4], rm[4], rvs[4], bb[4];
#pragma unroll
    for (int j = 0; j < 4; j++) {
        int c = tx * 4 + j;
        gam[j] = bn[c]; bet[j] = bn[64 + c]; rm[j] = bn[128 + c];
        rvs[j] = rsqrtf(bn[192 + c] + EPSBN);
        bb[j] = bias[c];
    }
#pragma unroll
    for (int i = 0; i < 4; i++) {
        int r = r0 + ty * 4 + i;
        if (r < n) {
            float v0 = fmaxf((acc[i][0] + bb[0] - rm[0]) * rvs[0] * gam[0] + bet[0], 0.f);
            float v1 = fmaxf((acc[i][1] + bb[1] - rm[1]) * rvs[1] * gam[1] + bet[1], 0.f);
            float v2 = fmaxf((acc[i][2] + bb[2] - rm[2]) * rvs[2] * gam[2] + bet[2], 0.f);
            float v3 = fmaxf((acc[i][3] + bb[3] - rm[3]) * rvs[3] * gam[3] + bet[3], 0.f);
            *(float4*)&out[(long)r * H + tx * 4] = make_float4(v0, v1, v2, v3);
            if (out16) {
                out16[r * 32 + tx * 2]     = __floats2bfloat162_rn(v0, v1);
                out16[r * 32 + tx * 2 + 1] = __floats2bfloat162_rn(v2, v3);
            }
        }
    }
}

// ---------------- fused aggregations ----------------
// Layer 1: one gather of h16 serves both branches.
//   aG[d] = dinv_d * (sum_s dinv_s*h_s + dinv_d*h_d)   (GCN pre-GEMM)
//   aS[d] = mean_s h_s                                  (SAGE pre-GEMM)
__global__ void k_agg1(const __nv_bfloat162* __restrict__ h16,
                       float2* __restrict__ aG, float2* __restrict__ aS, int n) {
    int d = blockIdx.x * 8 + (threadIdx.x >> 5);
    int lane = threadIdx.x & 31;
    if (d >= n) return;
    int beg = g_rowptr[d], end = g_rowptr[d + 1];
    float sgx = 0.f, sgy = 0.f, ssx = 0.f, ssy = 0.f;
    int j = beg;
    for (; j + 3 < end; j += 4) {
        int s0 = g_col[j], s1 = g_col[j + 1], s2 = g_col[j + 2], s3 = g_col[j + 3];
        float w0 = g_dinv[s0], w1 = g_dinv[s1], w2 = g_dinv[s2], w3 = g_dinv[s3];
        float2 f0 = __bfloat1622float2(h16[s0 * 32 + lane]);
        float2 f1 = __bfloat1622float2(h16[s1 * 32 + lane]);
        float2 f2 = __bfloat1622float2(h16[s2 * 32 + lane]);
        float2 f3 = __bfloat1622float2(h16[s3 * 32 + lane]);
        ssx += (f0.x + f1.x) + (f2.x + f3.x);
        ssy += (f0.y + f1.y) + (f2.y + f3.y);
        sgx += w0 * f0.x + w1 * f1.x + w2 * f2.x + w3 * f3.x;
        sgy += w0 * f0.y + w1 * f1.y + w2 * f2.y + w3 * f3.y;
    }
    for (; j < end; j++) {
        int s = g_col[j];
        float w = g_dinv[s];
        float2 f = __bfloat1622float2(h16[s * 32 + lane]);
        ssx += f.x; ssy += f.y;
        sgx += w * f.x; sgy += w * f.y;
    }
    float wd = g_dinv[d];
    float2 fd = __bfloat1622float2(h16[d * 32 + lane]);
    sgx = (sgx + wd * fd.x) * wd;
    sgy = (sgy + wd * fd.y) * wd;
    float inv = 1.f / fmaxf((float)(end - beg), 1.f);
    aG[d * 32 + lane] = make_float2(sgx, sgy);
    aS[d * 32 + lane] = make_float2(ssx * inv, ssy * inv);
}

// Layer 2: fused gather of both staged arrays over the same CSR.
//   hg16 holds dinv_s*hg_s already -> aG[d] = dinv_d * (sum_s hg16_s + hg16_d)
//   aS[d] = mean_s hs16_s
__global__ void k_agg2(const __nv_bfloat162* __restrict__ hg16,
                       const __nv_bfloat162* __restrict__ hs16,
                       float2* __restrict__ aG, float2* __restrict__ aS, int n) {
    int d = blockIdx.x * 8 + (threadIdx.x >> 5);
    int lane = threadIdx.x & 31;
    if (d >= n) return;
    int beg = g_rowptr[d], end = g_rowptr[d + 1];
    float gx = 0.f, gy = 0.f, sx = 0.f, sy = 0.f;
    int j = beg;
    for (; j + 3 < end; j += 4) {
        int s0 = g_col[j], s1 = g_col[j + 1], s2 = g_col[j + 2], s3 = g_col[j + 3];
        float2 a0 = __bfloat1622float2(hg16[s0 * 32 + lane]);
        float2 a1 = __bfloat1622float2(hg16[s1 * 32 + lane]);
        float2 a2 = __bfloat1622float2(hg16[s2 * 32 + lane]);
        float2 a3 = __bfloat1622float2(hg16[s3 * 32 + lane]);
        float2 b0 = __bfloat1622float2(hs16[s0 * 32 + lane]);
        float2 b1 = __bfloat1622float2(hs16[s1 * 32 + lane]);
        float2 b2 = __bfloat1622float2(hs16[s2 * 32 + lane]);
        float2 b3 = __bfloat1622float2(hs16[s3 * 32 + lane]);
        gx += (a0.x + a1.x) + (a2.x + a3.x);
        gy += (a0.y + a1.y) + (a2.y + a3.y);
        sx += (b0.x + b1.x) + (b2.x + b3.x);
        sy += (b0.y + b1.y) + (b2.y + b3.y);
    }
    for (; j < end; j++) {
        int s = g_col[j];
        float2 a = __bfloat1622float2(hg16[s * 32 + lane]);
        float2 b = __bfloat1622float2(hs16[s * 32 + lane]);
        gx += a.x; gy += a.y;
        sx += b.x; sy += b.y;
    }
    float wd = g_dinv[d];
    float2 ad = __bfloat1622float2(hg16[d * 32 + lane]);
    gx = (gx + ad.x) * wd;
    gy = (gy + ad.y) * wd;
    float inv = 1.f / fmaxf((float)(end - beg), 1.f);
    aG[d * 32 + lane] = make_float2(gx, gy);
    aS[d * 32 + lane] = make_float2(sx * inv, sy * inv);
}

// ---------------- pooling (batch is sorted -> run-flush) ----------------
__global__ void k_pool(const float* __restrict__ hg, const float* __restrict__ hs,
                       const int* __restrict__ batch, int n) {
    int c = threadIdx.x & 63;
    int nl = threadIdx.x >> 6;
    int i0 = blockIdx.x * 256 + nl * 64;
    float ag = 0.f, as = 0.f;
    int cur = -1;
    for (int k = 0; k < 64; k++) {
        int i = i0 + k;
        if (i >= n) break;
        int g = batch[i];
        if (g != cur) {
            if (cur >= 0) {
                atomicAdd(&g_pool[cur * 128 + c], ag);
                atomicAdd(&g_pool[cur * 128 + 64 + c], as);
            }
            cur = g; ag = 0.f; as = 0.f;
        }
        ag += hg[(long)i * H + c];
        as += hs[(long)i * H + c];
    }
    if (cur >= 0) {
        atomicAdd(&g_pool[cur * 128 + c], ag);
        atomicAdd(&g_pool[cur * 128 + 64 + c], as);
    }
}

// ---------------- final MLP (one block per graph) ----------------
__global__ void k_mlp(const float* __restrict__ fc1W, const float* __restrict__ fc1b,
                      const float* __restrict__ bn1,
                      const float* __restrict__ fc2W, const float* __restrict__ fc2b,
                      const float* __restrict__ bn2,
                      const float* __restrict__ fc3W, const float* __restrict__ fc3b,
                      float* __restrict__ out) {
    int g = blockIdx.x;
    int t = threadIdx.x;  // 64 threads
    __shared__ float z[128];
    __shared__ float s1[64];
    __shared__ float s2[32];
    float inv = 1.f / fmaxf((float)g_gcnt[g], 1.f);
    z[t]      = g_pool[g * 128 + t] * inv;
    z[t + 64] = g_pool[g * 128 + 64 + t] * inv;
    __syncthreads();
    float acc = fc1b[t];
#pragma unroll 8
    for (int k = 0; k < 128; k++) acc += z[k] * fc1W[k * 64 + t];
    acc = (acc - bn1[128 + t]) * rsqrtf(bn1[192 + t] + EPSBN) * bn1[t] + bn1[64 + t];
    s1[t] = fmaxf(acc, 0.f);
    __syncthreads();
    if (t < 32) {
        float a = fc2b[t];
#pragma unroll 8
        for (int k = 0; k < 64; k++) a += s1[k] * fc2W[k * 32 + t];
        a = (a - bn2[64 + t]) * rsqrtf(bn2[96 + t] + EPSBN) * bn2[t] + bn2[32 + t];
        s2[t] = fmaxf(a, 0.f);
    }
    __syncthreads();
    if (t < 32) {
        float p = s2[t] * fc3W[t];
#pragma unroll
        for (int o = 16; o > 0; o >>= 1) p += __shfl_down_sync(0xffffffffu, p, o);
        if (t == 0) out[g] = p + fc3b[0];
    }
}

// ---------------- launch ----------------
extern "C" void kernel_launch(void* const* d_in, const int* in_sizes, int n_in,
                              void* d_out, int out_size) {
    const float* x     = (const float*)d_in[0];
    const int*   ei    = (const int*)d_in[1];
    const int*   batch = (const int*)d_in[2];
    const float* W_in  = (const float*)d_in[3];
    const float* b_in  = (const float*)d_in[4];
    const float* gcn_W = (const float*)d_in[5];
    const float* gcn_b = (const float*)d_in[6];
    const float* gcn_bn= (const float*)d_in[7];
    const float* sg_Wl = (const float*)d_in[8];
    const float* sg_Wr = (const float*)d_in[9];
    const float* sg_b  = (const float*)d_in[10];
    const float* sg_bn = (const float*)d_in[11];
    const float* fc1W  = (const float*)d_in[12];
    const float* fc1b  = (const float*)d_in[13];
    const float* bn1   = (const float*)d_in[14];
    const float* fc2W  = (const float*)d_in[15];
    const float* fc2b  = (const float*)d_in[16];
    const float* bn2   = (const float*)d_in[17];
    const float* fc3W  = (const float*)d_in[18];
    const float* fc3b  = (const float*)d_in[19];
    float* out = (float*)d_out;

    int N = in_sizes[0] / DIN;
    int E = in_sizes[1] / 2;
    int G = out_size;
    const int* src = ei;
    const int* dst = ei + E;

    float *d_h, *d_hs, *d_hg, *d_tG, *d_tS;
    __nv_bfloat162 *d_h16, *d_hg16, *d_hs16;
    cudaGetSymbolAddress((void**)&d_h,    g_h);
    cudaGetSymbolAddress((void**)&d_hs,   g_hs);
    cudaGetSymbolAddress((void**)&d_hg,   g_hg);
    cudaGetSymbolAddress((void**)&d_tG,   g_tG);
    cudaGetSymbolAddress((void**)&d_tS,   g_tS);
    cudaGetSymbolAddress((void**)&d_h16,  g_h16);
    cudaGetSymbolAddress((void**)&d_hg16, g_hg16);
    cudaGetSymbolAddress((void**)&d_hs16, g_hs16);

    int nbN   = (N + 255) / 256;
    int nbE   = ((E > N ? E : N) + 255) / 256;
    int nbG64 = (N + 63) / 64;
    int nbAgg = (N + 7) / 8;

    // CSR build + degrees
    k_zero<<<nbN, 256>>>(N, G);
    k_deg<<<nbE, 256>>>(dst, batch, E, N);
    k_scan1<<<nbN, 256>>>(N);
    k_scan2<<<1, 256>>>(nbN);
    k_rowptr<<<nbN, 256>>>(N);
    k_fill<<<(E + 255) / 256, 256>>>(src, dst, E);

    // input projection (fp32 + bf16 staged)
    k_gemm_in<<<nbG64, 256>>>(x, W_in, b_in, d_h, d_h16, N);

    // Layer 1: one fused gather feeds both branches
    k_agg1<<<nbAgg, 256>>>(d_h16, (float2*)d_tG, (float2*)d_tS, N);
    // GCN L1 GEMM: only staged bf16 output needed (prescaled by dinv for L2 gather)
    k_gcn_gemm<<<nbG64, 256>>>(d_tG, gcn_W, gcn_b, gcn_bn, nullptr, d_hg16, N);
    // SAGE L1 GEMM: fp32 hs (needed for L2 Wr term) + staged bf16
    k_sage_gemm<<<nbG64, 256>>>(d_tS, sg_Wl, d_h, sg_Wr, sg_b, sg_bn, d_hs, d_hs16, N);

    // Layer 2: fused gather of both staged arrays
    k_agg2<<<nbAgg, 256>>>(d_hg16, d_hs16, (float2*)d_tG, (float2*)d_tS, N);
    k_gcn_gemm<<<nbG64, 256>>>(d_tG, gcn_W + 64 * 64, gcn_b + 64, gcn_bn + 256,
                               d_hg, nullptr, N);
    k_sage_gemm<<<nbG64, 256>>>(d_tS, sg_Wl + 64 * 64, d_hs, sg_Wr + 64 * 64,
                                sg_b + 64, sg_bn + 256, d_hs, nullptr, N);

    // pooling + MLP head
    k_pool<<<nbN, 256>>>(d_hg, d_hs, batch, N);
    k_mlp<<<G, 64>>>(fc1W, fc1b, bn1, fc2W, fc2b, bn2, fc3W, fc3b, out);
}

// round 5
// speedup vs baseline: 1.5401x; 1.2418x over previous
#include <cuda_runtime.h>
#include <cuda_bf16.h>
#include <math.h>

#define H      64
#define DIN    128
#define EPSBN  1e-5f
#define MAXN   50048
#define MAXE   1200128
#define MAXG   64

// ---------------- scratch (static __device__, no runtime allocs) ----------------
__device__ __nv_bfloat162 g_h16 [MAXN * 32];  // relu(x@W_in) bf16
__device__ __nv_bfloat162 g_hg16[MAXN * 32];  // dinv*hg (prescaled for L2 gather)
__device__ __nv_bfloat162 g_hs16[MAXN * 32];  // sage hidden bf16
__device__ __nv_bfloat162 g_aG16[MAXN * 32];  // gcn agg result bf16
__device__ __nv_bfloat162 g_aS16[MAXN * 32];  // sage agg result bf16
__device__ float g_hg [MAXN * H];             // gcn final fp32 (for pooling)
__device__ float g_hs [MAXN * H];             // sage final fp32 (for pooling)
__device__ int   g_indeg[MAXN];
__device__ int   g_fill [MAXN];
__device__ int   g_rowptr[MAXN + 1];
__device__ int   g_col  [MAXE];
__device__ float g_dinv [MAXN];
__device__ float g_pool [MAXG * 2 * H];
__device__ int   g_gcnt [MAXG];
__device__ int   g_scanbuf[MAXN];
__device__ int   g_blocksums[256];

// ---------------- setup kernels ----------------
__global__ void k_zero(int n, int g) {
    int i = blockIdx.x * blockDim.x + threadIdx.x;
    if (i < n) { g_indeg[i] = 0; g_fill[i] = 0; }
    if (i < g * 2 * H) g_pool[i] = 0.f;
    if (i < g) g_gcnt[i] = 0;
}

__global__ void k_deg(const int* __restrict__ dst, const int* __restrict__ batch,
                      int E, int N) {
    int i = blockIdx.x * blockDim.x + threadIdx.x;
    if (i < E) atomicAdd(&g_indeg[dst[i]], 1);
    if (i < N) atomicAdd(&g_gcnt[batch[i]], 1);
}

__global__ void k_scan1(int N) {
    __shared__ int sh[256];
    int t = threadIdx.x;
    int i = blockIdx.x * 256 + t;
    int v = (i < N) ? g_indeg[i] : 0;
    sh[t] = v; __syncthreads();
#pragma unroll
    for (int off = 1; off < 256; off <<= 1) {
        int a = 0;
        if (t >= off) a = sh[t - off];
        __syncthreads();
        sh[t] += a;
        __syncthreads();
    }
    if (i < N) {
        g_scanbuf[i] = sh[t];
        g_dinv[i] = rsqrtf((float)(v + 1));
    }
    if (t == 255) g_blocksums[blockIdx.x] = sh[255];
}

__global__ void k_scan2(int nb) {
    __shared__ int sh[256];
    int t = threadIdx.x;
    int v = (t < nb) ? g_blocksums[t] : 0;
    sh[t] = v; __syncthreads();
#pragma unroll
    for (int off = 1; off < 256; off <<= 1) {
        int a = 0;
        if (t >= off) a = sh[t - off];
        __syncthreads();
        sh[t] += a;
        __syncthreads();
    }
    if (t < nb) g_blocksums[t] = sh[t] - v;   // exclusive
}

__global__ void k_rowptr(int N) {
    int i = blockIdx.x * 256 + threadIdx.x;
    if (i < N) g_rowptr[i + 1] = g_scanbuf[i] + g_blocksums[blockIdx.x];
    if (i == 0) g_rowptr[0] = 0;
}

__global__ void k_fill(const int* __restrict__ src, const int* __restrict__ dst, int E) {
    int e = blockIdx.x * blockDim.x + threadIdx.x;
    if (e < E) {
        int d = dst[e];
        int pos = atomicAdd(&g_fill[d], 1);
        g_col[g_rowptr[d] + pos] = src[e];
    }
}

// ---------------- tensor-core GEMM: out[n,64] = relu(scale*(A@W) + shift) ----------------
// SRC: 0 = bf16 A0 (K=64), 1 = fp32 Af (K=128), 2 = concat bf16 [A0|A1] (K=128).
// W is fp32 [K,64] (SRC==2: W0 rows 0-63, W1 rows 64-127), converted+transposed to SMEM.
// bn nullable: scale=gamma*rsqrt(rv+eps), shift=(bias-rm)*scale+beta; else scale=1,shift=bias.
// outf nullable fp32 [n,64]; out16 nullable bf16 [n,32] (optionally prescaled by pre[row]).
template<int K, int SRC>
__global__ void __launch_bounds__(128)
k_mma(const float* __restrict__ Af,
      const __nv_bfloat16* __restrict__ A0,
      const __nv_bfloat16* __restrict__ A1,
      const float* __restrict__ W0,
      const float* __restrict__ W1,
      const float* __restrict__ bias,
      const float* __restrict__ bn,
      float* __restrict__ outf,
      __nv_bfloat162* __restrict__ out16,
      const float* __restrict__ pre,
      int n) {
    __shared__ __align__(16) __nv_bfloat16 As[64 * K];
    __shared__ __align__(16) __nv_bfloat16 Ws[64 * K];
    __shared__ float cscale[64], cshift[64];
    const int tid = threadIdx.x;
    const int r0 = blockIdx.x * 64;

    // ---- stage A (XOR-swizzled: half-offset = base ^ ((row&7)<<3)) ----
    if (SRC == 1) {
        // fp32 source, K floats per row; read float4, write 2x bf162
        for (int i = tid; i < 64 * (K / 4); i += 128) {
            int row = i / (K / 4), c4 = i % (K / 4);
            int r = r0 + row;
            float4 v = make_float4(0.f, 0.f, 0.f, 0.f);
            if (r < n) v = *(const float4*)(Af + (long)r * K + c4 * 4);
            int hoff = row * K + ((c4 * 4) ^ ((row & 7) << 3));
            __nv_bfloat162* p = (__nv_bfloat162*)&As[hoff];
            p[0] = __floats2bfloat162_rn(v.x, v.y);
            p[1] = __floats2bfloat162_rn(v.z, v.w);
        }
    } else {
        // bf16 source(s): copy 8 halves (uint4) at a time
        for (int i = tid; i < 64 * (K / 8); i += 128) {
            int row = i / (K / 8), c8 = i % (K / 8);
            int r = r0 + row;
            uint4 v = make_uint4(0, 0, 0, 0);
            if (r < n) {
                if (SRC == 2 && c8 >= 8) v = *(const uint4*)(A1 + (long)r * 64 + (c8 - 8) * 8);
                else                     v = *(const uint4*)(A0 + (long)r * 64 + c8 * 8);
            }
            int hoff = row * K + ((c8 * 8) ^ ((row & 7) << 3));
            *(uint4*)&As[hoff] = v;
        }
    }
    // ---- stage W transposed (Ws[nn][k]), bf16, same swizzle on k-words ----
    for (int i = tid; i < K * 64; i += 128) {
        int k = i >> 6, nn = i & 63;
        float w = (SRC == 2 && k >= 64) ? W1[(k - 64) * 64 + nn] : W0[k * 64 + nn];
        int word = (k >> 1) ^ ((nn & 7) << 2);
        Ws[nn * K + word * 2 + (k & 1)] = __float2bfloat16(w);
    }
    // ---- epilogue constants ----
    if (tid < 64) {
        float sc, sh;
        if (bn) {
            float rvs = rsqrtf(bn[192 + tid] + EPSBN);
            sc = bn[tid] * rvs;
            sh = (bias[tid] - bn[128 + tid]) * sc + bn[64 + tid];
        } else { sc = 1.f; sh = bias[tid]; }
        cscale[tid] = sc; cshift[tid] = sh;
    }
    __syncthreads();

    const int w = tid >> 5, lane = tid & 31;
    const int g = lane >> 2, t = lane & 3;
    const int rA = w * 16 + g;
    const unsigned* As32 = (const unsigned*)As;
    const unsigned* Ws32 = (const unsigned*)Ws;
    constexpr int SW = K / 2;   // words per row
    const int swz = g << 2;

    float c[8][4] = {};
#pragma unroll
    for (int k0 = 0; k0 < K; k0 += 16) {
        int kw0 = ((k0 >> 1) + t) ^ swz;
        int kw1 = ((k0 >> 1) + t + 4) ^ swz;
        unsigned a0 = As32[rA * SW + kw0];
        unsigned a1 = As32[(rA + 8) * SW + kw0];
        unsigned a2 = As32[rA * SW + kw1];
        unsigned a3 = As32[(rA + 8) * SW + kw1];
#pragma unroll
        for (int nt = 0; nt < 8; nt++) {
            unsigned b0 = Ws32[(nt * 8 + g) * SW + kw0];
            unsigned b1 = Ws32[(nt * 8 + g) * SW + kw1];
            asm volatile(
                "mma.sync.aligned.m16n8k16.row.col.f32.bf16.bf16.f32 "
                "{%0,%1,%2,%3}, {%4,%5,%6,%7}, {%8,%9}, {%0,%1,%2,%3};"
                : "+f"(c[nt][0]), "+f"(c[nt][1]), "+f"(c[nt][2]), "+f"(c[nt][3])
                : "r"(a0), "r"(a1), "r"(a2), "r"(a3), "r"(b0), "r"(b1));
        }
    }

    // ---- epilogue ----
    int row0 = r0 + w * 16 + g;
    int row1 = row0 + 8;
    float dv0 = 1.f, dv1 = 1.f;
    if (pre) {
        if (row0 < n) dv0 = pre[row0];
        if (row1 < n) dv1 = pre[row1];
    }
#pragma unroll
    for (int nt = 0; nt < 8; nt++) {
        int col = nt * 8 + 2 * t;
        float s0 = cscale[col], s1 = cscale[col + 1];
        float h0 = cshift[col], h1 = cshift[col + 1];
        float v00 = fmaxf(c[nt][0] * s0 + h0, 0.f);
        float v01 = fmaxf(c[nt][1] * s1 + h1, 0.f);
        float v10 = fmaxf(c[nt][2] * s0 + h0, 0.f);
        float v11 = fmaxf(c[nt][3] * s1 + h1, 0.f);
        if (row0 < n) {
            if (outf)  *(float2*)&outf[(long)row0 * 64 + col] = make_float2(v00, v01);
            if (out16) out16[row0 * 32 + (col >> 1)] = __floats2bfloat162_rn(v00 * dv0, v01 * dv0);
        }
        if (row1 < n) {
            if (outf)  *(float2*)&outf[(long)row1 * 64 + col] = make_float2(v10, v11);
            if (out16) out16[row1 * 32 + (col >> 1)] = __floats2bfloat162_rn(v10 * dv1, v11 * dv1);
        }
    }
}

// ---------------- fused aggregations (bf16 in, bf16 out, fp32 accumulate) ----------------
// Layer 1: aG[d] = dinv_d*(sum_s dinv_s*h_s + dinv_d*h_d);  aS[d] = mean_s h_s
__global__ void k_agg1(const __nv_bfloat162* __restrict__ h16,
                       __nv_bfloat162* __restrict__ aG, __nv_bfloat162* __restrict__ aS,
                       int n) {
    int d = blockIdx.x * 8 + (threadIdx.x >> 5);
    int lane = threadIdx.x & 31;
    if (d >= n) return;
    int beg = g_rowptr[d], end = g_rowptr[d + 1];
    float sgx = 0.f, sgy = 0.f, ssx = 0.f, ssy = 0.f;
    int j = beg;
    for (; j + 3 < end; j += 4) {
        int s0 = g_col[j], s1 = g_col[j + 1], s2 = g_col[j + 2], s3 = g_col[j + 3];
        float w0 = g_dinv[s0], w1 = g_dinv[s1], w2 = g_dinv[s2], w3 = g_dinv[s3];
        float2 f0 = __bfloat1622float2(h16[s0 * 32 + lane]);
        float2 f1 = __bfloat1622float2(h16[s1 * 32 + lane]);
        float2 f2 = __bfloat1622float2(h16[s2 * 32 + lane]);
        float2 f3 = __bfloat1622float2(h16[s3 * 32 + lane]);
        ssx += (f0.x + f1.x) + (f2.x + f3.x);
        ssy += (f0.y + f1.y) + (f2.y + f3.y);
        sgx += w0 * f0.x + w1 * f1.x + w2 * f2.x + w3 * f3.x;
        sgy += w0 * f0.y + w1 * f1.y + w2 * f2.y + w3 * f3.y;
    }
    for (; j < end; j++) {
        int s = g_col[j];
        float ww = g_dinv[s];
        float2 f = __bfloat1622float2(h16[s * 32 + lane]);
        ssx += f.x; ssy += f.y;
        sgx += ww * f.x; sgy += ww * f.y;
    }
    float wd = g_dinv[d];
    float2 fd = __bfloat1622float2(h16[d * 32 + lane]);
    sgx = (sgx + wd * fd.x) * wd;
    sgy = (sgy + wd * fd.y) * wd;
    float inv = 1.f / fmaxf((float)(end - beg), 1.f);
    aG[d * 32 + lane] = __floats2bfloat162_rn(sgx, sgy);
    aS[d * 32 + lane] = __floats2bfloat162_rn(ssx * inv, ssy * inv);
}

// Layer 2: hg16 prescaled by dinv_s -> aG[d] = dinv_d*(sum_s hg16_s + hg16_d); aS = mean hs16
__global__ void k_agg2(const __nv_bfloat162* __restrict__ hg16,
                       const __nv_bfloat162* __restrict__ hs16,
                       __nv_bfloat162* __restrict__ aG, __nv_bfloat162* __restrict__ aS,
                       int n) {
    int d = blockIdx.x * 8 + (threadIdx.x >> 5);
    int lane = threadIdx.x & 31;
    if (d >= n) return;
    int beg = g_rowptr[d], end = g_rowptr[d + 1];
    float gx = 0.f, gy = 0.f, sx = 0.f, sy = 0.f;
    int j = beg;
    for (; j + 3 < end; j += 4) {
        int s0 = g_col[j], s1 = g_col[j + 1], s2 = g_col[j + 2], s3 = g_col[j + 3];
        float2 a0 = __bfloat1622float2(hg16[s0 * 32 + lane]);
        float2 a1 = __bfloat1622float2(hg16[s1 * 32 + lane]);
        float2 a2 = __bfloat1622float2(hg16[s2 * 32 + lane]);
        float2 a3 = __bfloat1622float2(hg16[s3 * 32 + lane]);
        float2 b0 = __bfloat1622float2(hs16[s0 * 32 + lane]);
        float2 b1 = __bfloat1622float2(hs16[s1 * 32 + lane]);
        float2 b2 = __bfloat1622float2(hs16[s2 * 32 + lane]);
        float2 b3 = __bfloat1622float2(hs16[s3 * 32 + lane]);
        gx += (a0.x + a1.x) + (a2.x + a3.x);
        gy += (a0.y + a1.y) + (a2.y + a3.y);
        sx += (b0.x + b1.x) + (b2.x + b3.x);
        sy += (b0.y + b1.y) + (b2.y + b3.y);
    }
    for (; j < end; j++) {
        int s = g_col[j];
        float2 a = __bfloat1622float2(hg16[s * 32 + lane]);
        float2 b = __bfloat1622float2(hs16[s * 32 + lane]);
        gx += a.x; gy += a.y;
        sx += b.x; sy += b.y;
    }
    float wd = g_dinv[d];
    float2 ad = __bfloat1622float2(hg16[d * 32 + lane]);
    gx = (gx + ad.x) * wd;
    gy = (gy + ad.y) * wd;
    float inv = 1.f / fmaxf((float)(end - beg), 1.f);
    aG[d * 32 + lane] = __floats2bfloat162_rn(gx, gy);
    aS[d * 32 + lane] = __floats2bfloat162_rn(sx * inv, sy * inv);
}

// ---------------- pooling (batch is sorted -> run-flush) ----------------
__global__ void k_pool(const float* __restrict__ hg, const float* __restrict__ hs,
                       const int* __restrict__ batch, int n) {
    int c = threadIdx.x & 63;
    int nl = threadIdx.x >> 6;
    int i0 = blockIdx.x * 256 + nl * 64;
    float ag = 0.f, as = 0.f;
    int cur = -1;
    for (int k = 0; k < 64; k++) {
        int i = i0 + k;
        if (i >= n) break;
        int g = batch[i];
        if (g != cur) {
            if (cur >= 0) {
                atomicAdd(&g_pool[cur * 128 + c], ag);
                atomicAdd(&g_pool[cur * 128 + 64 + c], as);
            }
            cur = g; ag = 0.f; as = 0.f;
        }
        ag += hg[(long)i * H + c];
        as += hs[(long)i * H + c];
    }
    if (cur >= 0) {
        atomicAdd(&g_pool[cur * 128 + c], ag);
        atomicAdd(&g_pool[cur * 128 + 64 + c], as);
    }
}

// ---------------- final MLP (one block per graph) ----------------
__global__ void k_mlp(const float* __restrict__ fc1W, const float* __restrict__ fc1b,
                      const float* __restrict__ bn1,
                      const float* __restrict__ fc2W, const float* __restrict__ fc2b,
                      const float* __restrict__ bn2,
                      const float* __restrict__ fc3W, const float* __restrict__ fc3b,
                      float* __restrict__ out) {
    int g = blockIdx.x;
    int t = threadIdx.x;  // 64 threads
    __shared__ float z[128];
    __shared__ float s1[64];
    __shared__ float s2[32];
    float inv = 1.f / fmaxf((float)g_gcnt[g], 1.f);
    z[t]      = g_pool[g * 128 + t] * inv;
    z[t + 64] = g_pool[g * 128 + 64 + t] * inv;
    __syncthreads();
    float acc = fc1b[t];
#pragma unroll 8
    for (int k = 0; k < 128; k++) acc += z[k] * fc1W[k * 64 + t];
    acc = (acc - bn1[128 + t]) * rsqrtf(bn1[192 + t] + EPSBN) * bn1[t] + bn1[64 + t];
    s1[t] = fmaxf(acc, 0.f);
    __syncthreads();
    if (t < 32) {
        float a = fc2b[t];
#pragma unroll 8
        for (int k = 0; k < 64; k++) a += s1[k] * fc2W[k * 32 + t];
        a = (a - bn2[64 + t]) * rsqrtf(bn2[96 + t] + EPSBN) * bn2[t] + bn2[32 + t];
        s2[t] = fmaxf(a, 0.f);
    }
    __syncthreads();
    if (t < 32) {
        float p = s2[t] * fc3W[t];
#pragma unroll
        for (int o = 16; o > 0; o >>= 1) p += __shfl_down_sync(0xffffffffu, p, o);
        if (t == 0) out[g] = p + fc3b[0];
    }
}

// ---------------- launch ----------------
extern "C" void kernel_launch(void* const* d_in, const int* in_sizes, int n_in,
                              void* d_out, int out_size) {
    const float* x     = (const float*)d_in[0];
    const int*   ei    = (const int*)d_in[1];
    const int*   batch = (const int*)d_in[2];
    const float* W_in  = (const float*)d_in[3];
    const float* b_in  = (const float*)d_in[4];
    const float* gcn_W = (const float*)d_in[5];
    const float* gcn_b = (const float*)d_in[6];
    const float* gcn_bn= (const float*)d_in[7];
    const float* sg_Wl = (const float*)d_in[8];
    const float* sg_Wr = (const float*)d_in[9];
    const float* sg_b  = (const float*)d_in[10];
    const float* sg_bn = (const float*)d_in[11];
    const float* fc1W  = (const float*)d_in[12];
    const float* fc1b  = (const float*)d_in[13];
    const float* bn1   = (const float*)d_in[14];
    const float* fc2W  = (const float*)d_in[15];
    const float* fc2b  = (const float*)d_in[16];
    const float* bn2   = (const float*)d_in[17];
    const float* fc3W  = (const float*)d_in[18];
    const float* fc3b  = (const float*)d_in[19];
    float* out = (float*)d_out;

    int N = in_sizes[0] / DIN;
    int E = in_sizes[1] / 2;
    int G = out_size;
    const int* src = ei;
    const int* dst = ei + E;

    float *d_hg, *d_hs, *d_dinv;
    __nv_bfloat162 *d_h16, *d_hg16, *d_hs16, *d_aG16, *d_aS16;
    cudaGetSymbolAddress((void**)&d_hg,   g_hg);
    cudaGetSymbolAddress((void**)&d_hs,   g_hs);
    cudaGetSymbolAddress((void**)&d_dinv, g_dinv);
    cudaGetSymbolAddress((void**)&d_h16,  g_h16);
    cudaGetSymbolAddress((void**)&d_hg16, g_hg16);
    cudaGetSymbolAddress((void**)&d_hs16, g_hs16);
    cudaGetSymbolAddress((void**)&d_aG16, g_aG16);
    cudaGetSymbolAddress((void**)&d_aS16, g_aS16);

    int nbN   = (N + 255) / 256;
    int nbE   = ((E > N ? E : N) + 255) / 256;
    int nb64  = (N + 63) / 64;
    int nbAgg = (N + 7) / 8;

    // CSR build + degrees
    k_zero<<<nbN, 256>>>(N, G);
    k_deg<<<nbE, 256>>>(dst, batch, E, N);
    k_scan1<<<nbN, 256>>>(N);
    k_scan2<<<1, 256>>>(nbN);
    k_rowptr<<<nbN, 256>>>(N);
    k_fill<<<(E + 255) / 256, 256>>>(src, dst, E);

    // input projection: h16 = relu(x @ W_in + b_in)   (fp32 src, K=128)
    k_mma<128, 1><<<nb64, 128>>>(x, nullptr, nullptr, W_in, nullptr, b_in,
                                 nullptr, nullptr, d_h16, nullptr, N);

    // Layer 1: one fused gather feeds both branches
    k_agg1<<<nbAgg, 256>>>(d_h16, d_aG16, d_aS16, N);
    // GCN L1: hg16 = dinv * relu(BN(aG @ W0 + b))
    k_mma<64, 0><<<nb64, 128>>>(nullptr, (const __nv_bfloat16*)d_aG16, nullptr,
                                gcn_W, nullptr, gcn_b, gcn_bn,
                                nullptr, d_hg16, d_dinv, N);
    // SAGE L1: hs16 = relu(BN([aS|h] @ [Wl;Wr] + b))
    k_mma<128, 2><<<nb64, 128>>>(nullptr, (const __nv_bfloat16*)d_aS16,
                                 (const __nv_bfloat16*)d_h16,
                                 sg_Wl, sg_Wr, sg_b, sg_bn,
                                 nullptr, d_hs16, nullptr, N);

    // Layer 2: fused gather of both staged arrays
    k_agg2<<<nbAgg, 256>>>(d_hg16, d_hs16, d_aG16, d_aS16, N);
    // GCN L2 -> fp32 hg
    k_mma<64, 0><<<nb64, 128>>>(nullptr, (const __nv_bfloat16*)d_aG16, nullptr,
                                gcn_W + 64 * 64, nullptr, gcn_b + 64, gcn_bn + 256,
                                d_hg, nullptr, nullptr, N);
    // SAGE L2 -> fp32 hs
    k_mma<128, 2><<<nb64, 128>>>(nullptr, (const __nv_bfloat16*)d_aS16,
                                 (const __nv_bfloat16*)d_hs16,
                                 sg_Wl + 64 * 64, sg_Wr + 64 * 64, sg_b + 64, sg_bn + 256,
                                 d_hs, nullptr, nullptr, N);

    // pooling + MLP head
    k_pool<<<nbN, 256>>>(d_hg, d_hs, batch, N);
    k_mlp<<<G, 64>>>(fc1W, fc1b, bn1, fc2W, fc2b, bn2, fc3W, fc3b, out);
}